// round 11
// baseline (speedup 1.0000x reference)
#include <cuda_runtime.h>
#include <math.h>

// Problem constants
#define NIMG 8
#define CCH  3
#define HI   512
#define WI   512
#define HO   2048
#define WO   2048

__device__ __forceinline__ float sigm(float z) {
    return 1.0f / (1.0f + expf(-z));
}

// Single fused kernel. Block covers 128x8 output px (one thread = 4 px in x).
// Warp 0 classifies all 8 layers against the block ONCE (exact monotone tests
// at block corner pixels -> per-layer {disjoint, straddle, block-interior}),
// producing a process mask and an interior mask. The per-thread layer loop
// then only touches layers that can matter (typically 1-2), eliminating the
// serial 8-iteration smem-dependent reject chain.
// Back-to-front compositing: topmost block-interior layer (m==1 everywhere in
// the block) truncates the mask — everything beneath it and bg are invisible.
__global__ __launch_bounds__(256) void composite_kernel(
    const float* __restrict__ src,   // [8,3,512,512]
    const float* __restrict__ bg,    // [1,3,2048,2048]
    const float* __restrict__ coor,  // [8,4]
    float* __restrict__ out)         // [1,3,2048,2048]
{
    // Folded affine params: ix = ax*px + bx, iy = ay*py + by
    __shared__ float4 sprm[NIMG];
    __shared__ unsigned s_masks[2];   // [0]=process mask, [1]=block-interior mask

    const int ltid = threadIdx.y * 32 + threadIdx.x;
    const int blk_px0 = blockIdx.x * 128;
    const int blk_py0 = blockIdx.y * 8;

    if (ltid < 32) {
        const int n = ltid & 7;     // lanes 8-31 duplicate layers 0-7 (for ballot)
        float x = sigm(coor[4 * n + 0]) * (float)WO;
        float y = sigm(coor[4 * n + 1]) * (float)HO;
        float w = sigm(coor[4 * n + 2]) * (float)WO;
        float h = sigm(coor[4 * n + 3]) * (float)HO;
        float a  = (float)WO / (w + 1e-8f);
        float tx = (2.0f / (float)WO) * ((float)WO * 0.5f - x) * a;
        float b  = (float)HO / (h + 1e-8f);
        float ty = (2.0f / (float)HO) * ((float)HO * 0.5f - y) * b;
        // ix(px) = ((a*((2px+1)/WO - 1) + tx + 1)*WI - 1)/2 == ax*px + bx
        float ax = a * ((float)WI / (float)WO);
        float bx = ((a * (1.0f / (float)WO - 1.0f) + tx + 1.0f) * (float)WI - 1.0f) * 0.5f;
        float ay = b * ((float)HI / (float)HO);
        float by = ((b * (1.0f / (float)HO - 1.0f) + ty + 1.0f) * (float)HI - 1.0f) * 0.5f;
        if (ltid < 8) sprm[n] = make_float4(ax, bx, ay, by);

        // Exact block-corner tests (same fmaf arithmetic as the main loop;
        // RN rounding is monotone in px/py since ax,ay > 0, so these imply
        // every per-thread test in the block).
        const float iyT = fmaf(ay, (float)blk_py0,        by);
        const float iyB = fmaf(ay, (float)(blk_py0 + 7),  by);
        const float ixL = fmaf(ax, (float)blk_px0,        bx);
        const float ixR = fmaf(ax, (float)(blk_px0 + 127), bx);
        const bool covers = !(iyB <= -1.0f || iyT >= (float)HI ||
                              ixR <= -1.0f || ixL >= (float)WI);
        const bool blk_int = (iyT >= 0.0f) && (iyB < (float)(HI - 1)) &&
                             (ixL >= 0.0f) && (ixR < (float)(WI - 1));
        unsigned cov_m = __ballot_sync(0xffffffffu, covers) & 0xffu;
        unsigned int_m = __ballot_sync(0xffffffffu, blk_int) & 0xffu;
        if (ltid == 0) {
            unsigned keep = cov_m;
            if (int_m) {
                const int stop = 31 - __clz((int)int_m);  // topmost opaque layer
                keep &= ~((1u << stop) - 1u);             // drop layers below it
            }
            s_masks[0] = keep;
            s_masks[1] = int_m;
        }
    }
    __syncthreads();

    const unsigned proc = s_masks[0];
    const unsigned intm = s_masks[1];

    const int px0 = blk_px0 + threadIdx.x * 4;
    const int py  = blk_py0 + threadIdx.y;
    const int HW  = HO * WO;
    const int base = py * WO + px0;

    float A[3][4] = {{0.f,0.f,0.f,0.f},{0.f,0.f,0.f,0.f},{0.f,0.f,0.f,0.f}};
    float T[4] = {1.f, 1.f, 1.f, 1.f};

    const float fpy  = (float)py;
    const float fpx0 = (float)px0;

#pragma unroll
    for (int n = NIMG - 1; n >= 0; n--) {
        if (!(proc & (1u << n))) continue;

        const float4 p = sprm[n];   // ax, bx, ay, by
        const float iy  = fmaf(p.z, fpy, p.w);
        const float ixA = fmaf(p.x, fpx0, p.y);

        const bool blk_interior = (intm >> n) & 1u;

        if (blk_interior) {
            // Whole block inside: m == 1 for all px, no per-thread tests.
            const float y0f = floorf(iy);
            const float wy1 = iy - y0f;
            const float wy0 = 1.0f - wy1;
            const int   y0  = (int)y0f;
            const float* sbase = src + (size_t)n * CCH * HI * WI;
            const float* r0 = sbase + y0 * WI;
            const float* r1 = r0 + WI;
#pragma unroll
            for (int j = 0; j < 4; j++) {
                const float ix = fmaf(p.x, (float)j, ixA);
                const float x0f = floorf(ix);
                const float wx1 = ix - x0f;
                const float wx0 = 1.0f - wx1;
                const int   x0  = (int)x0f;
                const float w00 = wy0 * wx0, w10 = wy1 * wx0;
                const float w01 = wy0 * wx1, w11 = wy1 * wx1;
#pragma unroll
                for (int c = 0; c < CCH; c++) {
                    const float* rc0 = r0 + c * (HI * WI);
                    const float* rc1 = r1 + c * (HI * WI);
                    const float v00 = __ldg(rc0 + x0);
                    const float v10 = __ldg(rc1 + x0);
                    const float v01 = __ldg(rc0 + x0 + 1);
                    const float v11 = __ldg(rc1 + x0 + 1);
                    const float s = fmaf(v11, w11, fmaf(v10, w10,
                                    fmaf(v01, w01, v00 * w00)));
                    A[c][j] = fmaf(T[j], s, A[c][j]);
                }
                T[j] = 0.0f;
            }
            break;   // topmost opaque layer: mask had nothing below anyway
        }

        // Straddling layer: per-thread reject + interior/boundary paths.
        if (iy <= -1.0f || iy >= (float)HI) continue;
        const float ixB = fmaf(p.x, 3.0f, ixA);
        if (ixB <= -1.0f || ixA >= (float)WI) continue;

        const float y0f = floorf(iy);
        const float wy1 = iy - y0f;
        const float wy0 = 1.0f - wy1;
        const int   y0  = (int)y0f;
        const int   y1  = y0 + 1;
        const float* sbase = src + (size_t)n * CCH * HI * WI;

        const bool interior = (iy >= 0.0f) && (iy < (float)(HI - 1)) &&
                              (ixA >= 0.0f) && (ixB < (float)(WI - 1));

        if (interior) {
            const float* r0 = sbase + y0 * WI;
            const float* r1 = r0 + WI;
#pragma unroll
            for (int j = 0; j < 4; j++) {
                const float ix = fmaf(p.x, (float)j, ixA);
                const float x0f = floorf(ix);
                const float wx1 = ix - x0f;
                const float wx0 = 1.0f - wx1;
                const int   x0  = (int)x0f;
                const float w00 = wy0 * wx0, w10 = wy1 * wx0;
                const float w01 = wy0 * wx1, w11 = wy1 * wx1;
#pragma unroll
                for (int c = 0; c < CCH; c++) {
                    const float* rc0 = r0 + c * (HI * WI);
                    const float* rc1 = r1 + c * (HI * WI);
                    const float v00 = __ldg(rc0 + x0);
                    const float v10 = __ldg(rc1 + x0);
                    const float v01 = __ldg(rc0 + x0 + 1);
                    const float v11 = __ldg(rc1 + x0 + 1);
                    const float s = fmaf(v11, w11, fmaf(v10, w10,
                                    fmaf(v01, w01, v00 * w00)));
                    A[c][j] = fmaf(T[j], s, A[c][j]);
                }
                T[j] = 0.0f;
            }
            break;   // group fully opaque
        } else {
            // Boundary path: full reference semantics (validity + clamps).
            const float wyv0 = (y0 >= 0 && y0 < HI) ? wy0 : 0.0f;
            const float wyv1 = (y1 >= 0 && y1 < HI) ? wy1 : 0.0f;
            const int y0c = min(max(y0, 0), HI - 1);
            const int y1c = min(max(y1, 0), HI - 1);
            const float my = wyv0 + wyv1;
            const float* r0 = sbase + y0c * WI;
            const float* r1 = sbase + y1c * WI;
#pragma unroll
            for (int j = 0; j < 4; j++) {
                const float ix = fmaf(p.x, (float)j, ixA);
                const float x0f = floorf(ix);
                const float wx1 = ix - x0f;
                const float wx0 = 1.0f - wx1;
                const int   x0  = (int)x0f;
                const int   x1  = x0 + 1;
                const float wxv0 = (x0 >= 0 && x0 < WI) ? wx0 : 0.0f;
                const float wxv1 = (x1 >= 0 && x1 < WI) ? wx1 : 0.0f;
                const int x0c = min(max(x0, 0), WI - 1);
                const int x1c = min(max(x1, 0), WI - 1);

                const float m = my * (wxv0 + wxv1);
                if (m == 0.0f) continue;
                const float wgt = T[j] * m;
#pragma unroll
                for (int c = 0; c < CCH; c++) {
                    const float* rc0 = r0 + c * (HI * WI);
                    const float* rc1 = r1 + c * (HI * WI);
                    const float v00 = __ldg(rc0 + x0c);
                    const float v10 = __ldg(rc1 + x0c);
                    const float v01 = __ldg(rc0 + x1c);
                    const float v11 = __ldg(rc1 + x1c);
                    const float rowA = v00 * wyv0 + v10 * wyv1;
                    const float rowB = v01 * wyv0 + v11 * wyv1;
                    const float s = rowA * wxv0 + rowB * wxv1;
                    A[c][j] = fmaf(wgt, s, A[c][j]);
                }
                T[j] *= (1.0f - m);
            }
        }
    }

    // Background contribution only where transparency survives.
    const float Tm = fmaxf(fmaxf(T[0], T[1]), fmaxf(T[2], T[3]));
    if (Tm > 0.0f) {
        const float4 b0 = *reinterpret_cast<const float4*>(bg + base);
        const float4 b1 = *reinterpret_cast<const float4*>(bg + HW + base);
        const float4 b2 = *reinterpret_cast<const float4*>(bg + 2 * HW + base);
        A[0][0] = fmaf(b0.x, T[0], A[0][0]);
        A[0][1] = fmaf(b0.y, T[1], A[0][1]);
        A[0][2] = fmaf(b0.z, T[2], A[0][2]);
        A[0][3] = fmaf(b0.w, T[3], A[0][3]);
        A[1][0] = fmaf(b1.x, T[0], A[1][0]);
        A[1][1] = fmaf(b1.y, T[1], A[1][1]);
        A[1][2] = fmaf(b1.z, T[2], A[1][2]);
        A[1][3] = fmaf(b1.w, T[3], A[1][3]);
        A[2][0] = fmaf(b2.x, T[0], A[2][0]);
        A[2][1] = fmaf(b2.y, T[1], A[2][1]);
        A[2][2] = fmaf(b2.z, T[2], A[2][2]);
        A[2][3] = fmaf(b2.w, T[3], A[2][3]);
    }

    *reinterpret_cast<float4*>(out + base) =
        make_float4(A[0][0], A[0][1], A[0][2], A[0][3]);
    *reinterpret_cast<float4*>(out + HW + base) =
        make_float4(A[1][0], A[1][1], A[1][2], A[1][3]);
    *reinterpret_cast<float4*>(out + 2 * HW + base) =
        make_float4(A[2][0], A[2][1], A[2][2], A[2][3]);
}

extern "C" void kernel_launch(void* const* d_in, const int* in_sizes, int n_in,
                              void* d_out, int out_size) {
    const float* src  = (const float*)d_in[0];  // [8,3,512,512]
    const float* bg   = (const float*)d_in[1];  // [1,3,2048,2048]
    const float* coor = (const float*)d_in[2];  // [8,4]
    float* out = (float*)d_out;                 // [1,3,2048,2048]

    dim3 block(32, 8);
    dim3 grid(WO / (4 * 32), HO / 8);   // (16, 256)
    composite_kernel<<<grid, block>>>(src, bg, coor, out);
}

// round 12
// speedup vs baseline: 1.1662x; 1.1662x over previous
#include <cuda_runtime.h>
#include <math.h>

// Problem constants
#define NIMG 8
#define CCH  3
#define HI   512
#define WI   512
#define HO   2048
#define WO   2048

__device__ __forceinline__ float sigm(float z) {
    return 1.0f / (1.0f + expf(-z));
}

__device__ __forceinline__ float4 ldcs4(const float* p) {
    return __ldcs(reinterpret_cast<const float4*>(p));
}
__device__ __forceinline__ void stcs4(float* p, float4 v) {
    __stcs(reinterpret_cast<float4*>(p), v);
}

// Single fused kernel: per-block param computation in shared memory, then
// back-to-front compositing with early termination (a fully-interior layer
// has m == 1 and overwrites everything below it).
// One thread = 4 consecutive x pixels; block (32,4) covers 128x4 px.
// Canvas traffic (bg reads, out writes) uses streaming cache hints (.cs) so
// the reused src images stay L2-resident.
__global__ __launch_bounds__(128) void composite_kernel(
    const float* __restrict__ src,   // [8,3,512,512]
    const float* __restrict__ bg,    // [1,3,2048,2048]
    const float* __restrict__ coor,  // [8,4]
    float* __restrict__ out)         // [1,3,2048,2048]
{
    // Folded affine params: ix = ax*px + bx, iy = ay*py + by
    __shared__ float4 sprm[NIMG];

    const int ltid = threadIdx.y * 32 + threadIdx.x;
    if (ltid < NIMG) {
        const int n = ltid;
        float x = sigm(coor[4 * n + 0]) * (float)WO;
        float y = sigm(coor[4 * n + 1]) * (float)HO;
        float w = sigm(coor[4 * n + 2]) * (float)WO;
        float h = sigm(coor[4 * n + 3]) * (float)HO;
        float a  = (float)WO / (w + 1e-8f);
        float tx = (2.0f / (float)WO) * ((float)WO * 0.5f - x) * a;
        float b  = (float)HO / (h + 1e-8f);
        float ty = (2.0f / (float)HO) * ((float)HO * 0.5f - y) * b;
        // ix(px) = ((a*((2px+1)/WO - 1) + tx + 1)*WI - 1)/2  ==  ax*px + bx
        float ax = a * ((float)WI / (float)WO);
        float bx = ((a * (1.0f / (float)WO - 1.0f) + tx + 1.0f) * (float)WI - 1.0f) * 0.5f;
        float ay = b * ((float)HI / (float)HO);
        float by = ((b * (1.0f / (float)HO - 1.0f) + ty + 1.0f) * (float)HI - 1.0f) * 0.5f;
        sprm[n] = make_float4(ax, bx, ay, by);
    }
    __syncthreads();

    const int px0 = (blockIdx.x * 32 + threadIdx.x) * 4;
    const int py  = blockIdx.y * 4 + threadIdx.y;
    const int HW  = HO * WO;
    const int base = py * WO + px0;

    float A[3][4] = {{0.f,0.f,0.f,0.f},{0.f,0.f,0.f,0.f},{0.f,0.f,0.f,0.f}};
    float T[4] = {1.f, 1.f, 1.f, 1.f};

    const float fpy  = (float)py;
    const float fpx0 = (float)px0;

#pragma unroll
    for (int n = NIMG - 1; n >= 0; n--) {
        const float4 p = sprm[n];   // ax, bx, ay, by

        const float iy = fmaf(p.z, fpy, p.w);
        if (iy <= -1.0f || iy >= (float)HI) continue;

        // group x-range reject (ax > 0, ix monotone in px)
        const float ixA = fmaf(p.x, fpx0, p.y);
        const float ixB = fmaf(p.x, 3.0f, ixA);
        if (ixB <= -1.0f || ixA >= (float)WI) continue;

        const float y0f = floorf(iy);
        const float wy1 = iy - y0f;
        const float wy0 = 1.0f - wy1;
        const int   y0  = (int)y0f;
        const int   y1  = y0 + 1;
        const float* sbase = src + (size_t)n * CCH * HI * WI;

        const bool interior = (iy >= 0.0f) && (iy < (float)(HI - 1)) &&
                              (ixA >= 0.0f) && (ixB < (float)(WI - 1));

        if (interior) {
            // m == 1 for all 4 px: this layer overwrites everything below.
            const float* r0 = sbase + y0 * WI;
            const float* r1 = r0 + WI;
#pragma unroll
            for (int j = 0; j < 4; j++) {
                const float ix = fmaf(p.x, (float)j, ixA);
                const float x0f = floorf(ix);
                const float wx1 = ix - x0f;
                const float wx0 = 1.0f - wx1;
                const int   x0  = (int)x0f;
                const float w00 = wy0 * wx0, w10 = wy1 * wx0;
                const float w01 = wy0 * wx1, w11 = wy1 * wx1;
#pragma unroll
                for (int c = 0; c < CCH; c++) {
                    const float* rc0 = r0 + c * (HI * WI);
                    const float* rc1 = r1 + c * (HI * WI);
                    const float v00 = __ldg(rc0 + x0);
                    const float v10 = __ldg(rc1 + x0);
                    const float v01 = __ldg(rc0 + x0 + 1);
                    const float v11 = __ldg(rc1 + x0 + 1);
                    const float s = fmaf(v11, w11, fmaf(v10, w10,
                                    fmaf(v01, w01, v00 * w00)));
                    A[c][j] = fmaf(T[j], s, A[c][j]);
                }
                T[j] = 0.0f;
            }
            break;   // group fully opaque: earlier layers + bg invisible
        } else {
            // Boundary path: full reference semantics (validity + clamps).
            const float wyv0 = (y0 >= 0 && y0 < HI) ? wy0 : 0.0f;
            const float wyv1 = (y1 >= 0 && y1 < HI) ? wy1 : 0.0f;
            const int y0c = min(max(y0, 0), HI - 1);
            const int y1c = min(max(y1, 0), HI - 1);
            const float my = wyv0 + wyv1;
            const float* r0 = sbase + y0c * WI;
            const float* r1 = sbase + y1c * WI;
#pragma unroll
            for (int j = 0; j < 4; j++) {
                const float ix = fmaf(p.x, (float)j, ixA);
                const float x0f = floorf(ix);
                const float wx1 = ix - x0f;
                const float wx0 = 1.0f - wx1;
                const int   x0  = (int)x0f;
                const int   x1  = x0 + 1;
                const float wxv0 = (x0 >= 0 && x0 < WI) ? wx0 : 0.0f;
                const float wxv1 = (x1 >= 0 && x1 < WI) ? wx1 : 0.0f;
                const int x0c = min(max(x0, 0), WI - 1);
                const int x1c = min(max(x1, 0), WI - 1);

                const float m = my * (wxv0 + wxv1);
                if (m == 0.0f) continue;
                const float wgt = T[j] * m;
#pragma unroll
                for (int c = 0; c < CCH; c++) {
                    const float* rc0 = r0 + c * (HI * WI);
                    const float* rc1 = r1 + c * (HI * WI);
                    const float v00 = __ldg(rc0 + x0c);
                    const float v10 = __ldg(rc1 + x0c);
                    const float v01 = __ldg(rc0 + x1c);
                    const float v11 = __ldg(rc1 + x1c);
                    const float rowA = v00 * wyv0 + v10 * wyv1;
                    const float rowB = v01 * wyv0 + v11 * wyv1;
                    const float s = rowA * wxv0 + rowB * wxv1;
                    A[c][j] = fmaf(wgt, s, A[c][j]);
                }
                T[j] *= (1.0f - m);
            }
        }
    }

    // Background contribution only where transparency survives.
    // Streaming loads: bg has zero reuse, keep it out of L2's working set.
    const float Tm = fmaxf(fmaxf(T[0], T[1]), fmaxf(T[2], T[3]));
    if (Tm > 0.0f) {
        const float4 b0 = ldcs4(bg + base);
        const float4 b1 = ldcs4(bg + HW + base);
        const float4 b2 = ldcs4(bg + 2 * HW + base);
        A[0][0] = fmaf(b0.x, T[0], A[0][0]);
        A[0][1] = fmaf(b0.y, T[1], A[0][1]);
        A[0][2] = fmaf(b0.z, T[2], A[0][2]);
        A[0][3] = fmaf(b0.w, T[3], A[0][3]);
        A[1][0] = fmaf(b1.x, T[0], A[1][0]);
        A[1][1] = fmaf(b1.y, T[1], A[1][1]);
        A[1][2] = fmaf(b1.z, T[2], A[1][2]);
        A[1][3] = fmaf(b1.w, T[3], A[1][3]);
        A[2][0] = fmaf(b2.x, T[0], A[2][0]);
        A[2][1] = fmaf(b2.y, T[1], A[2][1]);
        A[2][2] = fmaf(b2.z, T[2], A[2][2]);
        A[2][3] = fmaf(b2.w, T[3], A[2][3]);
    }

    // Streaming stores: out is written once, never re-read.
    stcs4(out + base,          make_float4(A[0][0], A[0][1], A[0][2], A[0][3]));
    stcs4(out + HW + base,     make_float4(A[1][0], A[1][1], A[1][2], A[1][3]));
    stcs4(out + 2 * HW + base, make_float4(A[2][0], A[2][1], A[2][2], A[2][3]));
}

extern "C" void kernel_launch(void* const* d_in, const int* in_sizes, int n_in,
                              void* d_out, int out_size) {
    const float* src  = (const float*)d_in[0];  // [8,3,512,512]
    const float* bg   = (const float*)d_in[1];  // [1,3,2048,2048]
    const float* coor = (const float*)d_in[2];  // [8,4]
    float* out = (float*)d_out;                 // [1,3,2048,2048]

    dim3 block(32, 4);                    // 128 threads
    dim3 grid(WO / (4 * 32), HO / 4);     // (16, 512) = 8192 blocks
    composite_kernel<<<grid, block>>>(src, bg, coor, out);
}